// round 2
// baseline (speedup 1.0000x reference)
#include <cuda_runtime.h>
#include <cuda_bf16.h>
#include <cstdint>

// Problem shape (reference): X [B=4, S=4096, D=2048] fp32.
// out[b,s,d] = X[b,s,d] + pe[s,d]
//   pe[s, 2i]   = sin(s / 10000^(2i/D))
//   pe[s, 2i+1] = cos(s / 10000^(2i/D))
//
// One thread handles one (s, d4) float4 of pe (pairs p0=2*d4, p0+1, i.e. elements
// {sin(a0), cos(a0), sin(a1), cos(a1)}) and applies it to all B batch images,
// amortizing the 2 exp2f + 2 sincosf across the batch and giving MLP=B on LDG.

namespace {
constexpr int S = 4096;
constexpr int D = 2048;
constexpr int D4 = D / 4;                               // 512 float4 per row
constexpr long long BATCH_STRIDE4 = (long long)S * D4;  // float4 elems per batch image

__global__ __launch_bounds__(256) void pe_add_kernel(
    const float4* __restrict__ x, float4* __restrict__ out, int nbatch)
{
    const int t = blockIdx.x * blockDim.x + threadIdx.x;   // 0 .. S*D4-1
    const int s  = t >> 9;        // t / 512
    const int d4 = t & (D4 - 1);  // t % 512

    const float pos = (float)s;

    // inv_freq(p) = 10000^(-2p/D) = 2^((-2p/D) * log2(10000))
    const float c = -(2.0f / (float)D) * 13.2877123795494493f;  // log2(10000)
    const int p0 = 2 * d4;
    const float f0 = exp2f(c * (float)p0);
    const float f1 = exp2f(c * (float)(p0 + 1));

    float s0, c0, s1, c1;
    sincosf(pos * f0, &s0, &c0);   // accurate range reduction (angles up to ~4095 rad)
    sincosf(pos * f1, &s1, &c1);

    const float4 pe = make_float4(s0, c0, s1, c1);

    for (int b = 0; b < nbatch; ++b) {
        const long long idx = (long long)b * BATCH_STRIDE4 + t;
        float4 v = x[idx];
        v.x += pe.x;
        v.y += pe.y;
        v.z += pe.z;
        v.w += pe.w;
        out[idx] = v;
    }
}
} // namespace

extern "C" void kernel_launch(void* const* d_in, const int* in_sizes, int n_in,
                              void* d_out, int out_size)
{
    (void)n_in; (void)out_size;
    const float4* x = (const float4*)d_in[0];
    float4* out = (float4*)d_out;

    const int nbatch = in_sizes[0] / (S * D);  // 4 for the reference shape
    const int total_threads = S * D4;          // 2,097,152
    const int block = 256;
    const int grid = total_threads / block;    // 8192
    pe_add_kernel<<<grid, block>>>(x, out, nbatch);
}

// round 3
// speedup vs baseline: 1.0014x; 1.0014x over previous
#include <cuda_runtime.h>
#include <cuda_bf16.h>
#include <cstdint>

// Problem shape (reference): X [B=4, S=4096, D=2048] fp32.
// out[b,s,d] = X[b,s,d] + pe[s,d]
//   pe[s, 2i]   = sin(s / 10000^(2i/D))
//   pe[s, 2i+1] = cos(s / 10000^(2i/D))
//
// One thread handles one (s, d4) float4 of pe (pairs p0=2*d4, p0+1, i.e. elements
// {sin(a0), cos(a0), sin(a1), cos(a1)}) and applies it to all B batch images,
// amortizing the 2 exp2f + 2 sincosf across the batch and giving MLP=B on LDG.

namespace {
constexpr int S = 4096;
constexpr int D = 2048;
constexpr int D4 = D / 4;                               // 512 float4 per row
constexpr long long BATCH_STRIDE4 = (long long)S * D4;  // float4 elems per batch image

__global__ __launch_bounds__(256) void pe_add_kernel(
    const float4* __restrict__ x, float4* __restrict__ out, int nbatch)
{
    const int t = blockIdx.x * blockDim.x + threadIdx.x;   // 0 .. S*D4-1
    const int s  = t >> 9;        // t / 512
    const int d4 = t & (D4 - 1);  // t % 512

    const float pos = (float)s;

    // inv_freq(p) = 10000^(-2p/D) = 2^((-2p/D) * log2(10000))
    const float c = -(2.0f / (float)D) * 13.2877123795494493f;  // log2(10000)
    const int p0 = 2 * d4;
    const float f0 = exp2f(c * (float)p0);
    const float f1 = exp2f(c * (float)(p0 + 1));

    float s0, c0, s1, c1;
    sincosf(pos * f0, &s0, &c0);   // accurate range reduction (angles up to ~4095 rad)
    sincosf(pos * f1, &s1, &c1);

    const float4 pe = make_float4(s0, c0, s1, c1);

    for (int b = 0; b < nbatch; ++b) {
        const long long idx = (long long)b * BATCH_STRIDE4 + t;
        float4 v = x[idx];
        v.x += pe.x;
        v.y += pe.y;
        v.z += pe.z;
        v.w += pe.w;
        out[idx] = v;
    }
}
} // namespace

extern "C" void kernel_launch(void* const* d_in, const int* in_sizes, int n_in,
                              void* d_out, int out_size)
{
    (void)n_in; (void)out_size;
    const float4* x = (const float4*)d_in[0];
    float4* out = (float4*)d_out;

    const int nbatch = in_sizes[0] / (S * D);  // 4 for the reference shape
    const int total_threads = S * D4;          // 2,097,152
    const int block = 256;
    const int grid = total_threads / block;    // 8192
    pe_add_kernel<<<grid, block>>>(x, out, nbatch);
}